// round 5
// baseline (speedup 1.0000x reference)
#include <cuda_runtime.h>
#include <cuda_bf16.h>
#include <math_constants.h>
#include <cstdint>

#define B_N 32768
#define D_N 128
#define K_N 4096
#define CAP 64
#define DELTA_C 2.5e-4f
#define NTILES 32

// phase-1 smem layout (bytes). Rows padded to 272B (136 bf16) for conflict-free LDSM.
#define ROWB 272
#define XS_OFF   0
#define E0_OFF   34816
#define E1_OFF   69632
#define SCNT_OFF 104448
#define TMAX_OFF 104960
#define SM_TOTAL 105984

__device__ __nv_bfloat16 g_xb[B_N * D_N];
__device__ __nv_bfloat16 g_eb[K_N * D_N];
__device__ int    g_cand[(size_t)B_N * CAP];
__device__ int    g_ccnt[B_N];
__device__ int    g_argmin[B_N];
__device__ float  g_esq[K_N];
__device__ int    g_counts[K_N];
__device__ double g_sum_e, g_sum_q;

__device__ __forceinline__ uint32_t smem_u32(const void* p) {
    uint32_t a;
    asm("{ .reg .u64 t; cvta.to.shared.u64 t, %1; cvt.u32.u64 %0, t; }"
        : "=r"(a) : "l"(p));
    return a;
}
__device__ __forceinline__ void ldsm_x4(uint32_t& r0, uint32_t& r1,
                                        uint32_t& r2, uint32_t& r3, uint32_t addr) {
    asm volatile("ldmatrix.sync.aligned.m8n8.x4.shared.b16 {%0,%1,%2,%3}, [%4];"
        : "=r"(r0), "=r"(r1), "=r"(r2), "=r"(r3) : "r"(addr));
}
__device__ __forceinline__ void mma16816(float* c, uint32_t a0, uint32_t a1,
                                         uint32_t a2, uint32_t a3,
                                         uint32_t b0, uint32_t b1) {
    asm volatile("mma.sync.aligned.m16n8k16.row.col.f32.bf16.bf16.f32 "
        "{%0,%1,%2,%3}, {%4,%5,%6,%7}, {%8,%9}, {%0,%1,%2,%3};"
        : "+f"(c[0]), "+f"(c[1]), "+f"(c[2]), "+f"(c[3])
        : "r"(a0), "r"(a1), "r"(a2), "r"(a3), "r"(b0), "r"(b1));
}

// ---------------------------------------------------------------------------
// fp32 -> bf16 (rn) for X and E
// ---------------------------------------------------------------------------
__global__ void k_convert(const float* __restrict__ X, const float* __restrict__ E) {
    int g = blockIdx.x * blockDim.x + threadIdx.x;   // one 8-elem group
    const int NXG = B_N * D_N / 8;
    const int NEG = K_N * D_N / 8;
    const float4* src;
    uint4* dst;
    int h;
    if (g < NXG)            { src = (const float4*)X; dst = (uint4*)g_xb; h = g; }
    else if (g < NXG + NEG) { src = (const float4*)E; dst = (uint4*)g_eb; h = g - NXG; }
    else return;
    float4 a = src[h * 2], b = src[h * 2 + 1];
    uint4 o;
    o.x = ((uint32_t)__bfloat16_as_ushort(__float2bfloat16_rn(a.y)) << 16) |
           (uint32_t)__bfloat16_as_ushort(__float2bfloat16_rn(a.x));
    o.y = ((uint32_t)__bfloat16_as_ushort(__float2bfloat16_rn(a.w)) << 16) |
           (uint32_t)__bfloat16_as_ushort(__float2bfloat16_rn(a.z));
    o.z = ((uint32_t)__bfloat16_as_ushort(__float2bfloat16_rn(b.y)) << 16) |
           (uint32_t)__bfloat16_as_ushort(__float2bfloat16_rn(b.x));
    o.w = ((uint32_t)__bfloat16_as_ushort(__float2bfloat16_rn(b.w)) << 16) |
           (uint32_t)__bfloat16_as_ushort(__float2bfloat16_rn(b.z));
    dst[h] = o;
}

// ---------------------------------------------------------------------------
// init: zero accumulators, |e_k|^2 (fp64 -> fp32)
// ---------------------------------------------------------------------------
__global__ void k_init(const float* __restrict__ E) {
    int k = blockIdx.x * blockDim.x + threadIdx.x;
    if (k < K_N) {
        g_counts[k] = 0;
        const float* row = E + (size_t)k * D_N;
        double s = 0.0;
        #pragma unroll 8
        for (int d = 0; d < D_N; d++) { double v = (double)row[d]; s += v * v; }
        g_esq[k] = (float)s;
    }
    if (k == 0) { g_sum_e = 0.0; g_sum_q = 0.0; }
}

// ---------------------------------------------------------------------------
// phase1: bf16 mma.sync GEMM C = X_b @ E_b^T, global per-row prefix-max
// threshold candidate selection. 256 thr = 8 warps (4 m x 2 n), warp 32x64.
// ---------------------------------------------------------------------------
__global__ void __launch_bounds__(256, 2) k_phase1() {
    extern __shared__ char smem[];
    int*   scnt = (int*)  (smem + SCNT_OFF);   // [128]
    float* tmax = (float*)(smem + TMAX_OFF);   // [128][2]

    const int tid  = threadIdx.x;
    const int lane = tid & 31;
    const int wid  = tid >> 5;
    const int wm   = wid >> 1;          // 0..3  (rows 32*wm .. +32)
    const int wn   = wid & 1;           // 0..1  (cols 64*wn .. +64)
    const int row0 = blockIdx.x * 128;

    if (tid < 128) scnt[tid] = 0;

    const uint4* xg = (const uint4*)g_xb;   // 16 uint4 per 128-elem row
    const uint4* eg = (const uint4*)g_eb;

    // X tile (persistent) + E tile 0
    #pragma unroll
    for (int i = 0; i < 8; i++) {
        int m = tid + i * 256; int r = m >> 4, c16 = m & 15;
        *(uint4*)(smem + XS_OFF + r * ROWB + c16 * 16) = xg[(size_t)(row0 + r) * 16 + c16];
    }
    #pragma unroll
    for (int i = 0; i < 8; i++) {
        int m = tid + i * 256; int r = m >> 4, c16 = m & 15;
        *(uint4*)(smem + E0_OFF + r * ROWB + c16 * 16) = eg[(size_t)r * 16 + c16];
    }
    __syncthreads();

    const uint32_t sb = smem_u32(smem);
    const uint32_t pA = sb + XS_OFF + (uint32_t)((wm * 32 + (lane & 15)) * ROWB)
                        + (uint32_t)((lane >> 4) * 8 * 2);
    const int n_lane = ((lane >> 4) << 3) + (lane & 7);
    const uint32_t pB_off = (uint32_t)((wn * 64 + n_lane) * ROWB)
                            + (uint32_t)(((lane >> 3) & 1) * 8 * 2);

    const int qr = lane >> 2;           // quad row id 0..7
    const int qc = lane & 3;

    // global per-row running maxima (each lane tracks its qr rows)
    float thrA[2] = { -CUDART_INF_F, -CUDART_INF_F };
    float thrB[2] = { -CUDART_INF_F, -CUDART_INF_F };

    for (int t = 0; t < NTILES; t++) {
        const int buf = t & 1;
        const uint32_t pB = sb + (buf ? E1_OFF : E0_OFF) + pB_off;

        // prefetch next E tile into registers
        uint4 pf[8];
        if (t + 1 < NTILES) {
            #pragma unroll
            for (int i = 0; i < 8; i++) {
                int m = tid + i * 256; int r = m >> 4, c16 = m & 15;
                pf[i] = eg[(size_t)((t + 1) * 128 + r) * 16 + c16];
            }
        }

        float acc[2][8][4];
        #pragma unroll
        for (int mt = 0; mt < 2; mt++)
            #pragma unroll
            for (int nt = 0; nt < 8; nt++)
                #pragma unroll
                for (int j = 0; j < 4; j++) acc[mt][nt][j] = 0.0f;

        #pragma unroll
        for (int s = 0; s < 8; s++) {
            uint32_t a[2][4];
            #pragma unroll
            for (int mt = 0; mt < 2; mt++)
                ldsm_x4(a[mt][0], a[mt][1], a[mt][2], a[mt][3],
                        pA + (uint32_t)(mt * 16 * ROWB) + (uint32_t)(s * 32));
            uint32_t b[4][4];
            #pragma unroll
            for (int p = 0; p < 4; p++)
                ldsm_x4(b[p][0], b[p][1], b[p][2], b[p][3],
                        pB + (uint32_t)(p * 16 * ROWB) + (uint32_t)(s * 32));
            #pragma unroll
            for (int mt = 0; mt < 2; mt++)
                #pragma unroll
                for (int nt = 0; nt < 8; nt++) {
                    uint32_t b0 = (nt & 1) ? b[nt >> 1][2] : b[nt >> 1][0];
                    uint32_t b1 = (nt & 1) ? b[nt >> 1][3] : b[nt >> 1][1];
                    mma16816(acc[mt][nt], a[mt][0], a[mt][1], a[mt][2], a[mt][3], b0, b1);
                }
        }

        // stage next E tile (other buffer; its readers finished before last sync)
        if (t + 1 < NTILES) {
            char* eb = smem + (buf ? E0_OFF : E1_OFF);
            #pragma unroll
            for (int i = 0; i < 8; i++) {
                int m = tid + i * 256; int r = m >> 4, c16 = m & 15;
                *(uint4*)(eb + r * ROWB + c16 * 16) = pf[i];
            }
        }

        // ---- epilogue: warp-half row maxima -> smem exchange -> global cut ----
        float ma[2], mb[2];
        #pragma unroll
        for (int mt = 0; mt < 2; mt++) {
            float a_ = -CUDART_INF_F, b_ = -CUDART_INF_F;
            #pragma unroll
            for (int nt = 0; nt < 8; nt++) {
                a_ = fmaxf(a_, fmaxf(acc[mt][nt][0], acc[mt][nt][1]));
                b_ = fmaxf(b_, fmaxf(acc[mt][nt][2], acc[mt][nt][3]));
            }
            a_ = fmaxf(a_, __shfl_xor_sync(0xffffffffu, a_, 1));
            a_ = fmaxf(a_, __shfl_xor_sync(0xffffffffu, a_, 2));
            b_ = fmaxf(b_, __shfl_xor_sync(0xffffffffu, b_, 1));
            b_ = fmaxf(b_, __shfl_xor_sync(0xffffffffu, b_, 2));
            ma[mt] = a_; mb[mt] = b_;
        }
        if (qc == 0) {
            #pragma unroll
            for (int mt = 0; mt < 2; mt++) {
                int rA = wm * 32 + mt * 16 + qr;
                tmax[rA * 2 + wn] = ma[mt];
                tmax[(rA + 8) * 2 + wn] = mb[mt];
            }
        }
        __syncthreads();

        #pragma unroll
        for (int mt = 0; mt < 2; mt++) {
            const int rA = wm * 32 + mt * 16 + qr;
            const int rB = rA + 8;
            thrA[mt] = fmaxf(thrA[mt], fmaxf(tmax[rA * 2], tmax[rA * 2 + 1]));
            thrB[mt] = fmaxf(thrB[mt], fmaxf(tmax[rB * 2], tmax[rB * 2 + 1]));
            const float cutA = thrA[mt] - DELTA_C;
            const float cutB = thrB[mt] - DELTA_C;
            #pragma unroll
            for (int nt = 0; nt < 8; nt++) {
                int kb = t * 128 + wn * 64 + nt * 8 + 2 * qc;
                if (acc[mt][nt][0] >= cutA) {
                    int p = atomicAdd(&scnt[rA], 1);
                    if (p < CAP) g_cand[(size_t)(row0 + rA) * CAP + p] = kb;
                }
                if (acc[mt][nt][1] >= cutA) {
                    int p = atomicAdd(&scnt[rA], 1);
                    if (p < CAP) g_cand[(size_t)(row0 + rA) * CAP + p] = kb + 1;
                }
                if (acc[mt][nt][2] >= cutB) {
                    int p = atomicAdd(&scnt[rB], 1);
                    if (p < CAP) g_cand[(size_t)(row0 + rB) * CAP + p] = kb;
                }
                if (acc[mt][nt][3] >= cutB) {
                    int p = atomicAdd(&scnt[rB], 1);
                    if (p < CAP) g_cand[(size_t)(row0 + rB) * CAP + p] = kb + 1;
                }
            }
        }
        __syncthreads();
    }

    if (tid < 128) g_ccnt[row0 + tid] = scnt[tid];
}

// ---------------------------------------------------------------------------
// rescore: exact fp32 distances (reference rounding) over candidates.
// 8 lanes per row, 4 rows per warp, 32 rows per CTA. Each lane runs TWO
// interleaved candidate chains (per-candidate FMA order identical to R1-R4).
// Tie -> lowest index.
// ---------------------------------------------------------------------------
__global__ void __launch_bounds__(256) k_rescore(
    const float* __restrict__ X, const float* __restrict__ E)
{
    __shared__ float xs[32][132];
    const int warp = threadIdx.x >> 5;
    const int lane = threadIdx.x & 31;
    const int grp  = lane >> 3;     // 0..3: row within warp
    const int l8   = lane & 7;      // lane within 8-lane group
    const int rowL = warp * 4 + grp;
    const int row  = blockIdx.x * 32 + rowL;

    for (int i = threadIdx.x; i < 32 * 32; i += 256) {
        int r = i >> 5, c = i & 31;
        float4 v = ((const float4*)X)[(size_t)(blockIdx.x * 32 + r) * 32 + c];
        *(float4*)&xs[r][c * 4] = v;
    }
    __syncthreads();

    const float* xr = xs[rowL];
    // A = |x|^2 in fp64, reduced within the 8-lane group
    double s = 0.0;
    #pragma unroll
    for (int i = 0; i < 16; i++) { double v = (double)xr[l8 * 16 + i]; s += v * v; }
    #pragma unroll
    for (int off = 1; off < 8; off <<= 1)
        s += __shfl_xor_sync(0xffffffffu, s, off);
    float A = (float)s;

    int n = g_ccnt[row];
    float best = CUDART_INF_F;
    int bi = 0x7fffffff;

    if (n <= CAP) {
        for (int j = l8; j < n; j += 16) {
            int k1 = g_cand[(size_t)row * CAP + j];
            bool has2 = (j + 8) < n;
            int k2 = has2 ? g_cand[(size_t)row * CAP + j + 8] : k1;
            const float4* e1 = (const float4*)(E + (size_t)k1 * D_N);
            const float4* e2 = (const float4*)(E + (size_t)k2 * D_N);
            float a1 = 0.0f, a2 = 0.0f;
            #pragma unroll 8
            for (int i = 0; i < 32; i++) {
                float4 xv = *(const float4*)&xr[i * 4];
                float4 v1 = e1[i], v2 = e2[i];
                a1 = __fmaf_rn(xv.x, v1.x, a1);  a2 = __fmaf_rn(xv.x, v2.x, a2);
                a1 = __fmaf_rn(xv.y, v1.y, a1);  a2 = __fmaf_rn(xv.y, v2.y, a2);
                a1 = __fmaf_rn(xv.z, v1.z, a1);  a2 = __fmaf_rn(xv.z, v2.z, a2);
                a1 = __fmaf_rn(xv.w, v1.w, a1);  a2 = __fmaf_rn(xv.w, v2.w, a2);
            }
            float t1 = __fadd_rn(A, g_esq[k1]);
            float v1 = __fmaf_rn(-2.0f, a1, t1);
            if (v1 < best || (v1 == best && k1 < bi)) { best = v1; bi = k1; }
            if (has2) {
                float t2 = __fadd_rn(A, g_esq[k2]);
                float v2 = __fmaf_rn(-2.0f, a2, t2);
                if (v2 < best || (v2 == best && k2 < bi)) { best = v2; bi = k2; }
            }
        }
    } else {
        // safety fallback: exact full scan
        for (int k = l8; k < K_N; k += 8) {
            const float4* e4 = (const float4*)(E + (size_t)k * D_N);
            float acc = 0.0f;
            #pragma unroll 8
            for (int i = 0; i < 32; i++) {
                float4 xv = *(const float4*)&xr[i * 4];
                float4 ev = e4[i];
                acc = __fmaf_rn(xv.x, ev.x, acc);
                acc = __fmaf_rn(xv.y, ev.y, acc);
                acc = __fmaf_rn(xv.z, ev.z, acc);
                acc = __fmaf_rn(xv.w, ev.w, acc);
            }
            float tsum = __fadd_rn(A, g_esq[k]);
            float v = __fmaf_rn(-2.0f, acc, tsum);
            if (v < best || (v == best && k < bi)) { best = v; bi = k; }
        }
    }
    // butterfly reduce within 8-lane group, lexicographic (v, k)
    #pragma unroll
    for (int off = 1; off < 8; off <<= 1) {
        float ov = __shfl_xor_sync(0xffffffffu, best, off);
        int   oi = __shfl_xor_sync(0xffffffffu, bi, off);
        if (ov < best || (ov == best && oi < bi)) { best = ov; bi = oi; }
    }
    if (l8 == 0) g_argmin[row] = bi;
}

// ---------------------------------------------------------------------------
// gather: quantized rows + straight-through output + loss sums + histogram
// ---------------------------------------------------------------------------
__global__ void k_gather(const float* __restrict__ X, const float* __restrict__ E,
                         float* __restrict__ out, int out_size)
{
    int g = blockIdx.x * blockDim.x + threadIdx.x;
    int b = g >> 5, j = g & 31;
    int idx = g_argmin[b];

    float4 q = ((const float4*)E)[(size_t)idx * 32 + j];
    float4 x = ((const float4*)X)[g];

    float4 o;
    double se = 0.0, sq = 0.0;
    {
        float de = __fsub_rn(q.x, x.x); float qs = __fadd_rn(x.x, de);
        float dq = __fsub_rn(qs, x.x);
        o.x = qs; se += (double)de * (double)de; sq += (double)dq * (double)dq;
    }
    {
        float de = __fsub_rn(q.y, x.y); float qs = __fadd_rn(x.y, de);
        float dq = __fsub_rn(qs, x.y);
        o.y = qs; se += (double)de * (double)de; sq += (double)dq * (double)dq;
    }
    {
        float de = __fsub_rn(q.z, x.z); float qs = __fadd_rn(x.z, de);
        float dq = __fsub_rn(qs, x.z);
        o.z = qs; se += (double)de * (double)de; sq += (double)dq * (double)dq;
    }
    {
        float de = __fsub_rn(q.w, x.w); float qs = __fadd_rn(x.w, de);
        float dq = __fsub_rn(qs, x.w);
        o.w = qs; se += (double)de * (double)de; sq += (double)dq * (double)dq;
    }
    ((float4*)out)[g] = o;

    if (j == 0) {
        atomicAdd(&g_counts[idx], 1);
        if (out_size >= B_N * D_N + B_N)
            out[(size_t)B_N * D_N + b] = (float)idx;
    }

    #pragma unroll
    for (int off = 16; off > 0; off >>= 1) {
        se += __shfl_down_sync(0xffffffffu, se, off);
        sq += __shfl_down_sync(0xffffffffu, sq, off);
    }
    __shared__ double swe[8], swq[8];
    int lane = threadIdx.x & 31, w = threadIdx.x >> 5;
    if (lane == 0) { swe[w] = se; swq[w] = sq; }
    __syncthreads();
    if (threadIdx.x == 0) {
        double te = 0.0, tq = 0.0;
        #pragma unroll
        for (int i = 0; i < 8; i++) { te += swe[i]; tq += swq[i]; }
        atomicAdd(&g_sum_e, te);
        atomicAdd(&g_sum_q, tq);
    }
}

// ---------------------------------------------------------------------------
// final: entropy + scalar outputs in one kernel (single CTA)
// ---------------------------------------------------------------------------
__global__ void k_final(float* __restrict__ out, int out_size) {
    if (out_size < B_N * D_N + B_N + 4) return;
    __shared__ double sh[512];
    int tid = threadIdx.x;
    double h = 0.0;
    #pragma unroll
    for (int r = 0; r < K_N / 512; r++) {
        int k = r * 512 + tid;
        float p = __fmul_rn((float)g_counts[k], 1.0f / 32768.0f);
        float t = __fmul_rn(p, logf(__fadd_rn(p, 1e-10f)));
        h += (double)t;
    }
    sh[tid] = h;
    __syncthreads();
    for (int s = 256; s > 0; s >>= 1) {
        if (tid < s) sh[tid] += sh[tid + s];
        __syncthreads();
    }
    if (tid == 0) {
        float H = (float)sh[0];
        float perp = expf(-H);
        double n = (double)B_N * (double)D_N;
        float e = (float)(g_sum_e / n);
        float q = (float)(g_sum_q / n);
        float vq = __fadd_rn(q, __fmul_rn(0.25f, e));
        float* s4 = out + (size_t)B_N * D_N + B_N;
        s4[0] = vq; s4[1] = e; s4[2] = q; s4[3] = perp;
    }
}

// ---------------------------------------------------------------------------
extern "C" void kernel_launch(void* const* d_in, const int* in_sizes, int n_in,
                              void* d_out, int out_size)
{
    const float* X = (const float*)d_in[0];
    const float* E = (const float*)d_in[1];
    if (n_in >= 2 && in_sizes[0] == K_N * D_N && in_sizes[1] == B_N * D_N) {
        X = (const float*)d_in[1];
        E = (const float*)d_in[0];
    }
    float* out = (float*)d_out;

    static bool attr_set = false;
    if (!attr_set) {
        cudaFuncSetAttribute(k_phase1,
                             cudaFuncAttributeMaxDynamicSharedMemorySize,
                             SM_TOTAL);
        attr_set = true;
    }

    int ngroups = (B_N * D_N + K_N * D_N) / 8;
    k_convert<<<(ngroups + 255) / 256, 256>>>(X, E);
    k_init<<<(K_N + 255) / 256, 256>>>(E);
    k_phase1<<<B_N / 128, 256, SM_TOTAL>>>();
    k_rescore<<<B_N / 32, 256>>>(X, E);
    k_gather<<<(B_N * D_N / 4) / 256, 256>>>(X, E, out, out_size);
    k_final<<<1, 512>>>(out, out_size);
}

// round 6
// speedup vs baseline: 1.5109x; 1.5109x over previous
#include <cuda_runtime.h>
#include <cuda_bf16.h>
#include <math_constants.h>
#include <cstdint>

#define B_N 32768
#define D_N 128
#define K_N 4096
#define CAP 128
#define DELTA_C 2.5e-4f
#define NTILES 32

// phase-1 smem layout (bytes). Rows padded to 272B (136 bf16) for conflict-free LDSM.
#define ROWB 272
#define XS_OFF   0
#define E0_OFF   34816
#define E1_OFF   69632
#define SCNT_OFF 104448
#define SM_TOTAL 104960

__device__ __nv_bfloat16 g_xb[B_N * D_N];
__device__ __nv_bfloat16 g_eb[K_N * D_N];
__device__ int    g_cand[(size_t)B_N * CAP];
__device__ int    g_ccnt[B_N];
__device__ int    g_argmin[B_N];
__device__ float  g_esq[K_N];
__device__ int    g_counts[K_N];
__device__ double g_sum_e, g_sum_q, g_H;

__device__ __forceinline__ uint32_t smem_u32(const void* p) {
    uint32_t a;
    asm("{ .reg .u64 t; cvta.to.shared.u64 t, %1; cvt.u32.u64 %0, t; }"
        : "=r"(a) : "l"(p));
    return a;
}
__device__ __forceinline__ void ldsm_x4(uint32_t& r0, uint32_t& r1,
                                        uint32_t& r2, uint32_t& r3, uint32_t addr) {
    asm volatile("ldmatrix.sync.aligned.m8n8.x4.shared.b16 {%0,%1,%2,%3}, [%4];"
        : "=r"(r0), "=r"(r1), "=r"(r2), "=r"(r3) : "r"(addr));
}
__device__ __forceinline__ void mma16816(float* c, uint32_t a0, uint32_t a1,
                                         uint32_t a2, uint32_t a3,
                                         uint32_t b0, uint32_t b1) {
    asm volatile("mma.sync.aligned.m16n8k16.row.col.f32.bf16.bf16.f32 "
        "{%0,%1,%2,%3}, {%4,%5,%6,%7}, {%8,%9}, {%0,%1,%2,%3};"
        : "+f"(c[0]), "+f"(c[1]), "+f"(c[2]), "+f"(c[3])
        : "r"(a0), "r"(a1), "r"(a2), "r"(a3), "r"(b0), "r"(b1));
}

// ---------------------------------------------------------------------------
// fp32 -> bf16 (rn) for X and E
// ---------------------------------------------------------------------------
__global__ void k_convert(const float* __restrict__ X, const float* __restrict__ E) {
    int g = blockIdx.x * blockDim.x + threadIdx.x;   // one 8-elem group
    const int NXG = B_N * D_N / 8;
    const int NEG = K_N * D_N / 8;
    const float4* src;
    uint4* dst;
    int h;
    if (g < NXG)            { src = (const float4*)X; dst = (uint4*)g_xb; h = g; }
    else if (g < NXG + NEG) { src = (const float4*)E; dst = (uint4*)g_eb; h = g - NXG; }
    else return;
    float4 a = src[h * 2], b = src[h * 2 + 1];
    uint4 o;
    o.x = ((uint32_t)__bfloat16_as_ushort(__float2bfloat16_rn(a.y)) << 16) |
           (uint32_t)__bfloat16_as_ushort(__float2bfloat16_rn(a.x));
    o.y = ((uint32_t)__bfloat16_as_ushort(__float2bfloat16_rn(a.w)) << 16) |
           (uint32_t)__bfloat16_as_ushort(__float2bfloat16_rn(a.z));
    o.z = ((uint32_t)__bfloat16_as_ushort(__float2bfloat16_rn(b.y)) << 16) |
           (uint32_t)__bfloat16_as_ushort(__float2bfloat16_rn(b.x));
    o.w = ((uint32_t)__bfloat16_as_ushort(__float2bfloat16_rn(b.w)) << 16) |
           (uint32_t)__bfloat16_as_ushort(__float2bfloat16_rn(b.z));
    dst[h] = o;
}

// ---------------------------------------------------------------------------
// init: zero accumulators, |e_k|^2 (fp64 -> fp32)
// ---------------------------------------------------------------------------
__global__ void k_init(const float* __restrict__ E) {
    int k = blockIdx.x * blockDim.x + threadIdx.x;
    if (k < K_N) {
        g_counts[k] = 0;
        const float* row = E + (size_t)k * D_N;
        double s = 0.0;
        #pragma unroll 8
        for (int d = 0; d < D_N; d++) { double v = (double)row[d]; s += v * v; }
        g_esq[k] = (float)s;
    }
    if (k == 0) { g_sum_e = 0.0; g_sum_q = 0.0; g_H = 0.0; }
}

// ---------------------------------------------------------------------------
// phase1: bf16 mma.sync GEMM C = X_b @ E_b^T with per-half register-threshold
// candidate selection. 256 thr = 8 warps (4 m x 2 n), warp tile 32x64.
// (identical to the R4 kernel that measured 299.8us)
// ---------------------------------------------------------------------------
__global__ void __launch_bounds__(256, 2) k_phase1() {
    extern __shared__ char smem[];
    int* scnt = (int*)(smem + SCNT_OFF);   // [128]

    const int tid  = threadIdx.x;
    const int lane = tid & 31;
    const int wid  = tid >> 5;
    const int wm   = wid >> 1;          // 0..3  (rows 32*wm .. +32)
    const int wn   = wid & 1;           // 0..1  (cols 64*wn .. +64)
    const int row0 = blockIdx.x * 128;

    if (tid < 128) scnt[tid] = 0;

    const uint4* xg = (const uint4*)g_xb;   // 16 uint4 per 128-elem row
    const uint4* eg = (const uint4*)g_eb;

    // X tile (persistent) + E tile 0
    #pragma unroll
    for (int i = 0; i < 8; i++) {
        int m = tid + i * 256; int r = m >> 4, c16 = m & 15;
        *(uint4*)(smem + XS_OFF + r * ROWB + c16 * 16) = xg[(size_t)(row0 + r) * 16 + c16];
    }
    #pragma unroll
    for (int i = 0; i < 8; i++) {
        int m = tid + i * 256; int r = m >> 4, c16 = m & 15;
        *(uint4*)(smem + E0_OFF + r * ROWB + c16 * 16) = eg[(size_t)r * 16 + c16];
    }
    __syncthreads();

    const uint32_t sb = smem_u32(smem);
    const uint32_t pA = sb + XS_OFF + (uint32_t)((wm * 32 + (lane & 15)) * ROWB)
                        + (uint32_t)((lane >> 4) * 8 * 2);
    const int n_lane = ((lane >> 4) << 3) + (lane & 7);
    const uint32_t pB_off = (uint32_t)((wn * 64 + n_lane) * ROWB)
                            + (uint32_t)(((lane >> 3) & 1) * 8 * 2);

    const int qr = lane >> 2;           // quad row id 0..7
    const int qc = lane & 3;

    // per-half running row maxima (registers)
    float thrA[2] = { -CUDART_INF_F, -CUDART_INF_F };
    float thrB[2] = { -CUDART_INF_F, -CUDART_INF_F };

    for (int t = 0; t < NTILES; t++) {
        const int buf = t & 1;
        const uint32_t pB = sb + (buf ? E1_OFF : E0_OFF) + pB_off;

        // prefetch next E tile into registers
        uint4 pf[8];
        if (t + 1 < NTILES) {
            #pragma unroll
            for (int i = 0; i < 8; i++) {
                int m = tid + i * 256; int r = m >> 4, c16 = m & 15;
                pf[i] = eg[(size_t)((t + 1) * 128 + r) * 16 + c16];
            }
        }

        float acc[2][8][4];
        #pragma unroll
        for (int mt = 0; mt < 2; mt++)
            #pragma unroll
            for (int nt = 0; nt < 8; nt++)
                #pragma unroll
                for (int j = 0; j < 4; j++) acc[mt][nt][j] = 0.0f;

        #pragma unroll
        for (int s = 0; s < 8; s++) {
            uint32_t a[2][4];
            #pragma unroll
            for (int mt = 0; mt < 2; mt++)
                ldsm_x4(a[mt][0], a[mt][1], a[mt][2], a[mt][3],
                        pA + (uint32_t)(mt * 16 * ROWB) + (uint32_t)(s * 32));
            uint32_t b[4][4];
            #pragma unroll
            for (int p = 0; p < 4; p++)
                ldsm_x4(b[p][0], b[p][1], b[p][2], b[p][3],
                        pB + (uint32_t)(p * 16 * ROWB) + (uint32_t)(s * 32));
            #pragma unroll
            for (int mt = 0; mt < 2; mt++)
                #pragma unroll
                for (int nt = 0; nt < 8; nt++) {
                    uint32_t b0 = (nt & 1) ? b[nt >> 1][2] : b[nt >> 1][0];
                    uint32_t b1 = (nt & 1) ? b[nt >> 1][3] : b[nt >> 1][1];
                    mma16816(acc[mt][nt], a[mt][0], a[mt][1], a[mt][2], a[mt][3], b0, b1);
                }
        }

        // stage next E tile (writes go to the buffer last read at t-1; gated by sync)
        if (t + 1 < NTILES) {
            char* eb = smem + (buf ? E0_OFF : E1_OFF);
            #pragma unroll
            for (int i = 0; i < 8; i++) {
                int m = tid + i * 256; int r = m >> 4, c16 = m & 15;
                *(uint4*)(eb + r * ROWB + c16 * 16) = pf[i];
            }
        }

        // ---- epilogue: warp-local row maxima, per-half threshold, emission ----
        #pragma unroll
        for (int mt = 0; mt < 2; mt++) {
            float ma = -CUDART_INF_F, mb = -CUDART_INF_F;
            #pragma unroll
            for (int nt = 0; nt < 8; nt++) {
                ma = fmaxf(ma, fmaxf(acc[mt][nt][0], acc[mt][nt][1]));
                mb = fmaxf(mb, fmaxf(acc[mt][nt][2], acc[mt][nt][3]));
            }
            // reduce across the 4 quad-column lanes (xor 1,2 stays in quad)
            ma = fmaxf(ma, __shfl_xor_sync(0xffffffffu, ma, 1));
            ma = fmaxf(ma, __shfl_xor_sync(0xffffffffu, ma, 2));
            mb = fmaxf(mb, __shfl_xor_sync(0xffffffffu, mb, 1));
            mb = fmaxf(mb, __shfl_xor_sync(0xffffffffu, mb, 2));
            thrA[mt] = fmaxf(thrA[mt], ma);
            thrB[mt] = fmaxf(thrB[mt], mb);
            const float cutA = thrA[mt] - DELTA_C;
            const float cutB = thrB[mt] - DELTA_C;
            const int rA = wm * 32 + mt * 16 + qr;
            const int rB = rA + 8;
            #pragma unroll
            for (int nt = 0; nt < 8; nt++) {
                int kb = t * 128 + wn * 64 + nt * 8 + 2 * qc;
                if (acc[mt][nt][0] >= cutA) {
                    int p = atomicAdd(&scnt[rA], 1);
                    if (p < CAP) g_cand[(size_t)(row0 + rA) * CAP + p] = kb;
                }
                if (acc[mt][nt][1] >= cutA) {
                    int p = atomicAdd(&scnt[rA], 1);
                    if (p < CAP) g_cand[(size_t)(row0 + rA) * CAP + p] = kb + 1;
                }
                if (acc[mt][nt][2] >= cutB) {
                    int p = atomicAdd(&scnt[rB], 1);
                    if (p < CAP) g_cand[(size_t)(row0 + rB) * CAP + p] = kb;
                }
                if (acc[mt][nt][3] >= cutB) {
                    int p = atomicAdd(&scnt[rB], 1);
                    if (p < CAP) g_cand[(size_t)(row0 + rB) * CAP + p] = kb + 1;
                }
            }
        }
        __syncthreads();
    }

    if (tid < 128) g_ccnt[row0 + tid] = scnt[tid];
}

// ---------------------------------------------------------------------------
// rescore: exact fp32 distances (reference rounding) over candidates.
// 16 lanes per row, 2 rows per warp, 16 rows per CTA. Tie -> lowest index.
// Per-candidate arithmetic identical to R1-R4 (sequential 128-FMA chain).
// ---------------------------------------------------------------------------
__global__ void __launch_bounds__(256) k_rescore(
    const float* __restrict__ X, const float* __restrict__ E)
{
    __shared__ float xs[16][132];
    const int warp = threadIdx.x >> 5;
    const int lane = threadIdx.x & 31;
    const int grp  = lane >> 4;     // 0..1: row within warp
    const int l16  = lane & 15;     // lane within 16-lane group
    const int rowL = warp * 2 + grp;
    const int row  = blockIdx.x * 16 + rowL;

    for (int i = threadIdx.x; i < 16 * 32; i += 256) {
        int r = i >> 5, c = i & 31;
        float4 v = ((const float4*)X)[(size_t)(blockIdx.x * 16 + r) * 32 + c];
        *(float4*)&xs[r][c * 4] = v;
    }
    __syncthreads();

    const float* xr = xs[rowL];
    // A = |x|^2 in fp64, reduced within the 16-lane group
    double s = 0.0;
    #pragma unroll
    for (int i = 0; i < 8; i++) { double v = (double)xr[l16 * 8 + i]; s += v * v; }
    #pragma unroll
    for (int off = 1; off < 16; off <<= 1)
        s += __shfl_xor_sync(0xffffffffu, s, off);
    float A = (float)s;

    int n = g_ccnt[row];
    float best = CUDART_INF_F;
    int bi = 0x7fffffff;

    if (n <= CAP) {
        for (int j = l16; j < n; j += 16) {
            int k = g_cand[(size_t)row * CAP + j];
            const float4* e4 = (const float4*)(E + (size_t)k * D_N);
            float acc = 0.0f;
            #pragma unroll 8
            for (int i = 0; i < 32; i++) {
                float4 xv = *(const float4*)&xr[i * 4];
                float4 ev = e4[i];
                acc = __fmaf_rn(xv.x, ev.x, acc);
                acc = __fmaf_rn(xv.y, ev.y, acc);
                acc = __fmaf_rn(xv.z, ev.z, acc);
                acc = __fmaf_rn(xv.w, ev.w, acc);
            }
            float tsum = __fadd_rn(A, g_esq[k]);
            float v = __fmaf_rn(-2.0f, acc, tsum);
            if (v < best || (v == best && k < bi)) { best = v; bi = k; }
        }
    } else {
        // safety fallback: exact full scan (unreachable in practice with CAP=128)
        for (int k = l16; k < K_N; k += 16) {
            const float4* e4 = (const float4*)(E + (size_t)k * D_N);
            float acc = 0.0f;
            #pragma unroll 8
            for (int i = 0; i < 32; i++) {
                float4 xv = *(const float4*)&xr[i * 4];
                float4 ev = e4[i];
                acc = __fmaf_rn(xv.x, ev.x, acc);
                acc = __fmaf_rn(xv.y, ev.y, acc);
                acc = __fmaf_rn(xv.z, ev.z, acc);
                acc = __fmaf_rn(xv.w, ev.w, acc);
            }
            float tsum = __fadd_rn(A, g_esq[k]);
            float v = __fmaf_rn(-2.0f, acc, tsum);
            if (v < best || (v == best && k < bi)) { best = v; bi = k; }
        }
    }
    // butterfly reduce within 16-lane group, lexicographic (v, k)
    #pragma unroll
    for (int off = 1; off < 16; off <<= 1) {
        float ov = __shfl_xor_sync(0xffffffffu, best, off);
        int   oi = __shfl_xor_sync(0xffffffffu, bi, off);
        if (ov < best || (ov == best && oi < bi)) { best = ov; bi = oi; }
    }
    if (l16 == 0) g_argmin[row] = bi;
}

// ---------------------------------------------------------------------------
// gather: quantized rows + straight-through output + loss sums + histogram
// ---------------------------------------------------------------------------
__global__ void k_gather(const float* __restrict__ X, const float* __restrict__ E,
                         float* __restrict__ out, int out_size)
{
    int g = blockIdx.x * blockDim.x + threadIdx.x;
    int b = g >> 5, j = g & 31;
    int idx = g_argmin[b];

    float4 q = ((const float4*)E)[(size_t)idx * 32 + j];
    float4 x = ((const float4*)X)[g];

    float4 o;
    double se = 0.0, sq = 0.0;
    {
        float de = __fsub_rn(q.x, x.x); float qs = __fadd_rn(x.x, de);
        float dq = __fsub_rn(qs, x.x);
        o.x = qs; se += (double)de * (double)de; sq += (double)dq * (double)dq;
    }
    {
        float de = __fsub_rn(q.y, x.y); float qs = __fadd_rn(x.y, de);
        float dq = __fsub_rn(qs, x.y);
        o.y = qs; se += (double)de * (double)de; sq += (double)dq * (double)dq;
    }
    {
        float de = __fsub_rn(q.z, x.z); float qs = __fadd_rn(x.z, de);
        float dq = __fsub_rn(qs, x.z);
        o.z = qs; se += (double)de * (double)de; sq += (double)dq * (double)dq;
    }
    {
        float de = __fsub_rn(q.w, x.w); float qs = __fadd_rn(x.w, de);
        float dq = __fsub_rn(qs, x.w);
        o.w = qs; se += (double)de * (double)de; sq += (double)dq * (double)dq;
    }
    ((float4*)out)[g] = o;

    if (j == 0) {
        atomicAdd(&g_counts[idx], 1);
        if (out_size >= B_N * D_N + B_N)
            out[(size_t)B_N * D_N + b] = (float)idx;
    }

    #pragma unroll
    for (int off = 16; off > 0; off >>= 1) {
        se += __shfl_down_sync(0xffffffffu, se, off);
        sq += __shfl_down_sync(0xffffffffu, sq, off);
    }
    __shared__ double swe[8], swq[8];
    int lane = threadIdx.x & 31, w = threadIdx.x >> 5;
    if (lane == 0) { swe[w] = se; swq[w] = sq; }
    __syncthreads();
    if (threadIdx.x == 0) {
        double te = 0.0, tq = 0.0;
        #pragma unroll
        for (int i = 0; i < 8; i++) { te += swe[i]; tq += swq[i]; }
        atomicAdd(&g_sum_e, te);
        atomicAdd(&g_sum_q, tq);
    }
}

// ---------------------------------------------------------------------------
__global__ void k_entropy() {
    __shared__ double sh[256];
    int k = blockIdx.x * 256 + threadIdx.x;
    float p = __fmul_rn((float)g_counts[k], 1.0f / 32768.0f);
    float t = __fmul_rn(p, logf(__fadd_rn(p, 1e-10f)));
    sh[threadIdx.x] = (double)t;
    __syncthreads();
    for (int s = 128; s > 0; s >>= 1) {
        if (threadIdx.x < s) sh[threadIdx.x] += sh[threadIdx.x + s];
        __syncthreads();
    }
    if (threadIdx.x == 0) atomicAdd(&g_H, sh[0]);
}

__global__ void k_scalars(float* __restrict__ out, int out_size) {
    if (out_size < B_N * D_N + B_N + 4) return;
    float H = (float)g_H;
    float perp = expf(-H);
    double n = (double)B_N * (double)D_N;
    float e = (float)(g_sum_e / n);
    float q = (float)(g_sum_q / n);
    float vq = __fadd_rn(q, __fmul_rn(0.25f, e));
    float* s4 = out + (size_t)B_N * D_N + B_N;
    s4[0] = vq; s4[1] = e; s4[2] = q; s4[3] = perp;
}

// ---------------------------------------------------------------------------
extern "C" void kernel_launch(void* const* d_in, const int* in_sizes, int n_in,
                              void* d_out, int out_size)
{
    const float* X = (const float*)d_in[0];
    const float* E = (const float*)d_in[1];
    if (n_in >= 2 && in_sizes[0] == K_N * D_N && in_sizes[1] == B_N * D_N) {
        X = (const float*)d_in[1];
        E = (const float*)d_in[0];
    }
    float* out = (float*)d_out;

    static bool attr_set = false;
    if (!attr_set) {
        cudaFuncSetAttribute(k_phase1,
                             cudaFuncAttributeMaxDynamicSharedMemorySize,
                             SM_TOTAL);
        attr_set = true;
    }

    int ngroups = (B_N * D_N + K_N * D_N) / 8;
    k_convert<<<(ngroups + 255) / 256, 256>>>(X, E);
    k_init<<<(K_N + 255) / 256, 256>>>(E);
    k_phase1<<<B_N / 128, 256, SM_TOTAL>>>();
    k_rescore<<<B_N / 16, 256>>>(X, E);
    k_gather<<<(B_N * D_N / 4) / 256, 256>>>(X, E, out, out_size);
    k_entropy<<<K_N / 256, 256>>>();
    k_scalars<<<1, 1>>>(out, out_size);
}

// round 7
// speedup vs baseline: 1.7222x; 1.1399x over previous
#include <cuda_runtime.h>
#include <cuda_bf16.h>
#include <math_constants.h>
#include <cstdint>

#define B_N 32768
#define D_N 128
#define K_N 4096
#define CAP 128
#define DELTA_C 2.5e-4f
#define NTILES 32

// phase-1 smem layout (bytes). Rows padded to 272B (136 bf16) for conflict-free LDSM.
#define ROWB 272
#define XS_OFF   0
#define E0_OFF   34816
#define E1_OFF   69632
#define SCNT_OFF 104448
#define SM_TOTAL 104960

__device__ __nv_bfloat16 g_xb[B_N * D_N];
__device__ __nv_bfloat16 g_eb[K_N * D_N];
__device__ int2   g_cand[(size_t)B_N * CAP];   // .x = bf16-GEMM score bits, .y = index
__device__ int    g_ccnt[B_N];
__device__ int    g_argmin[B_N];
__device__ float  g_esq[K_N];
__device__ int    g_counts[K_N];
__device__ double g_sum_e, g_sum_q, g_H;

__device__ __forceinline__ uint32_t smem_u32(const void* p) {
    uint32_t a;
    asm("{ .reg .u64 t; cvta.to.shared.u64 t, %1; cvt.u32.u64 %0, t; }"
        : "=r"(a) : "l"(p));
    return a;
}
__device__ __forceinline__ void ldsm_x4(uint32_t& r0, uint32_t& r1,
                                        uint32_t& r2, uint32_t& r3, uint32_t addr) {
    asm volatile("ldmatrix.sync.aligned.m8n8.x4.shared.b16 {%0,%1,%2,%3}, [%4];"
        : "=r"(r0), "=r"(r1), "=r"(r2), "=r"(r3) : "r"(addr));
}
__device__ __forceinline__ void mma16816(float* c, uint32_t a0, uint32_t a1,
                                         uint32_t a2, uint32_t a3,
                                         uint32_t b0, uint32_t b1) {
    asm volatile("mma.sync.aligned.m16n8k16.row.col.f32.bf16.bf16.f32 "
        "{%0,%1,%2,%3}, {%4,%5,%6,%7}, {%8,%9}, {%0,%1,%2,%3};"
        : "+f"(c[0]), "+f"(c[1]), "+f"(c[2]), "+f"(c[3])
        : "r"(a0), "r"(a1), "r"(a2), "r"(a3), "r"(b0), "r"(b1));
}

// ---------------------------------------------------------------------------
// fp32 -> bf16 (rn) for X and E
// ---------------------------------------------------------------------------
__global__ void k_convert(const float* __restrict__ X, const float* __restrict__ E) {
    int g = blockIdx.x * blockDim.x + threadIdx.x;   // one 8-elem group
    const int NXG = B_N * D_N / 8;
    const int NEG = K_N * D_N / 8;
    const float4* src;
    uint4* dst;
    int h;
    if (g < NXG)            { src = (const float4*)X; dst = (uint4*)g_xb; h = g; }
    else if (g < NXG + NEG) { src = (const float4*)E; dst = (uint4*)g_eb; h = g - NXG; }
    else return;
    float4 a = src[h * 2], b = src[h * 2 + 1];
    uint4 o;
    o.x = ((uint32_t)__bfloat16_as_ushort(__float2bfloat16_rn(a.y)) << 16) |
           (uint32_t)__bfloat16_as_ushort(__float2bfloat16_rn(a.x));
    o.y = ((uint32_t)__bfloat16_as_ushort(__float2bfloat16_rn(a.w)) << 16) |
           (uint32_t)__bfloat16_as_ushort(__float2bfloat16_rn(a.z));
    o.z = ((uint32_t)__bfloat16_as_ushort(__float2bfloat16_rn(b.y)) << 16) |
           (uint32_t)__bfloat16_as_ushort(__float2bfloat16_rn(b.x));
    o.w = ((uint32_t)__bfloat16_as_ushort(__float2bfloat16_rn(b.w)) << 16) |
           (uint32_t)__bfloat16_as_ushort(__float2bfloat16_rn(b.z));
    dst[h] = o;
}

// ---------------------------------------------------------------------------
// init: zero accumulators, |e_k|^2 (fp64 -> fp32)
// ---------------------------------------------------------------------------
__global__ void k_init(const float* __restrict__ E) {
    int k = blockIdx.x * blockDim.x + threadIdx.x;
    if (k < K_N) {
        g_counts[k] = 0;
        const float* row = E + (size_t)k * D_N;
        double s = 0.0;
        #pragma unroll 8
        for (int d = 0; d < D_N; d++) { double v = (double)row[d]; s += v * v; }
        g_esq[k] = (float)s;
    }
    if (k == 0) { g_sum_e = 0.0; g_sum_q = 0.0; g_H = 0.0; }
}

// ---------------------------------------------------------------------------
// phase1: bf16 mma.sync GEMM C = X_b @ E_b^T with per-half register-threshold
// candidate selection; stores (score, index) pairs. Tile emission guarded by
// "tile max within delta of running max" (skips ~85% of emission loops).
// ---------------------------------------------------------------------------
__global__ void __launch_bounds__(256, 2) k_phase1() {
    extern __shared__ char smem[];
    int* scnt = (int*)(smem + SCNT_OFF);   // [128]

    const int tid  = threadIdx.x;
    const int lane = tid & 31;
    const int wid  = tid >> 5;
    const int wm   = wid >> 1;          // 0..3  (rows 32*wm .. +32)
    const int wn   = wid & 1;           // 0..1  (cols 64*wn .. +64)
    const int row0 = blockIdx.x * 128;

    if (tid < 128) scnt[tid] = 0;

    const uint4* xg = (const uint4*)g_xb;   // 16 uint4 per 128-elem row
    const uint4* eg = (const uint4*)g_eb;

    // X tile (persistent) + E tile 0
    #pragma unroll
    for (int i = 0; i < 8; i++) {
        int m = tid + i * 256; int r = m >> 4, c16 = m & 15;
        *(uint4*)(smem + XS_OFF + r * ROWB + c16 * 16) = xg[(size_t)(row0 + r) * 16 + c16];
    }
    #pragma unroll
    for (int i = 0; i < 8; i++) {
        int m = tid + i * 256; int r = m >> 4, c16 = m & 15;
        *(uint4*)(smem + E0_OFF + r * ROWB + c16 * 16) = eg[(size_t)r * 16 + c16];
    }
    __syncthreads();

    const uint32_t sb = smem_u32(smem);
    const uint32_t pA = sb + XS_OFF + (uint32_t)((wm * 32 + (lane & 15)) * ROWB)
                        + (uint32_t)((lane >> 4) * 8 * 2);
    const int n_lane = ((lane >> 4) << 3) + (lane & 7);
    const uint32_t pB_off = (uint32_t)((wn * 64 + n_lane) * ROWB)
                            + (uint32_t)(((lane >> 3) & 1) * 8 * 2);

    const int qr = lane >> 2;           // quad row id 0..7
    const int qc = lane & 3;

    // per-half running row maxima (registers)
    float thrA[2] = { -CUDART_INF_F, -CUDART_INF_F };
    float thrB[2] = { -CUDART_INF_F, -CUDART_INF_F };

    for (int t = 0; t < NTILES; t++) {
        const int buf = t & 1;
        const uint32_t pB = sb + (buf ? E1_OFF : E0_OFF) + pB_off;

        // prefetch next E tile into registers
        uint4 pf[8];
        if (t + 1 < NTILES) {
            #pragma unroll
            for (int i = 0; i < 8; i++) {
                int m = tid + i * 256; int r = m >> 4, c16 = m & 15;
                pf[i] = eg[(size_t)((t + 1) * 128 + r) * 16 + c16];
            }
        }

        float acc[2][8][4];
        #pragma unroll
        for (int mt = 0; mt < 2; mt++)
            #pragma unroll
            for (int nt = 0; nt < 8; nt++)
                #pragma unroll
                for (int j = 0; j < 4; j++) acc[mt][nt][j] = 0.0f;

        #pragma unroll
        for (int s = 0; s < 8; s++) {
            uint32_t a[2][4];
            #pragma unroll
            for (int mt = 0; mt < 2; mt++)
                ldsm_x4(a[mt][0], a[mt][1], a[mt][2], a[mt][3],
                        pA + (uint32_t)(mt * 16 * ROWB) + (uint32_t)(s * 32));
            uint32_t b[4][4];
            #pragma unroll
            for (int p = 0; p < 4; p++)
                ldsm_x4(b[p][0], b[p][1], b[p][2], b[p][3],
                        pB + (uint32_t)(p * 16 * ROWB) + (uint32_t)(s * 32));
            #pragma unroll
            for (int mt = 0; mt < 2; mt++)
                #pragma unroll
                for (int nt = 0; nt < 8; nt++) {
                    uint32_t b0 = (nt & 1) ? b[nt >> 1][2] : b[nt >> 1][0];
                    uint32_t b1 = (nt & 1) ? b[nt >> 1][3] : b[nt >> 1][1];
                    mma16816(acc[mt][nt], a[mt][0], a[mt][1], a[mt][2], a[mt][3], b0, b1);
                }
        }

        // stage next E tile (writes go to the buffer last read at t-1; gated by sync)
        if (t + 1 < NTILES) {
            char* eb = smem + (buf ? E0_OFF : E1_OFF);
            #pragma unroll
            for (int i = 0; i < 8; i++) {
                int m = tid + i * 256; int r = m >> 4, c16 = m & 15;
                *(uint4*)(eb + r * ROWB + c16 * 16) = pf[i];
            }
        }

        // ---- epilogue: warp-local row maxima, guarded emission ----
        #pragma unroll
        for (int mt = 0; mt < 2; mt++) {
            float ma = -CUDART_INF_F, mb = -CUDART_INF_F;
            #pragma unroll
            for (int nt = 0; nt < 8; nt++) {
                ma = fmaxf(ma, fmaxf(acc[mt][nt][0], acc[mt][nt][1]));
                mb = fmaxf(mb, fmaxf(acc[mt][nt][2], acc[mt][nt][3]));
            }
            // reduce across the 4 quad-column lanes (xor 1,2 stays in quad)
            ma = fmaxf(ma, __shfl_xor_sync(0xffffffffu, ma, 1));
            ma = fmaxf(ma, __shfl_xor_sync(0xffffffffu, ma, 2));
            mb = fmaxf(mb, __shfl_xor_sync(0xffffffffu, mb, 1));
            mb = fmaxf(mb, __shfl_xor_sync(0xffffffffu, mb, 2));
            // tile contributes iff tile-max >= old running max - delta
            const bool anyA = (ma >= thrA[mt] - DELTA_C);
            const bool anyB = (mb >= thrB[mt] - DELTA_C);
            thrA[mt] = fmaxf(thrA[mt], ma);
            thrB[mt] = fmaxf(thrB[mt], mb);
            const int rA = wm * 32 + mt * 16 + qr;
            const int rB = rA + 8;
            if (anyA) {
                const float cutA = thrA[mt] - DELTA_C;
                #pragma unroll
                for (int nt = 0; nt < 8; nt++) {
                    int kb = t * 128 + wn * 64 + nt * 8 + 2 * qc;
                    if (acc[mt][nt][0] >= cutA) {
                        int p = atomicAdd(&scnt[rA], 1);
                        if (p < CAP) g_cand[(size_t)(row0 + rA) * CAP + p] =
                            make_int2(__float_as_int(acc[mt][nt][0]), kb);
                    }
                    if (acc[mt][nt][1] >= cutA) {
                        int p = atomicAdd(&scnt[rA], 1);
                        if (p < CAP) g_cand[(size_t)(row0 + rA) * CAP + p] =
                            make_int2(__float_as_int(acc[mt][nt][1]), kb + 1);
                    }
                }
            }
            if (anyB) {
                const float cutB = thrB[mt] - DELTA_C;
                #pragma unroll
                for (int nt = 0; nt < 8; nt++) {
                    int kb = t * 128 + wn * 64 + nt * 8 + 2 * qc;
                    if (acc[mt][nt][2] >= cutB) {
                        int p = atomicAdd(&scnt[rB], 1);
                        if (p < CAP) g_cand[(size_t)(row0 + rB) * CAP + p] =
                            make_int2(__float_as_int(acc[mt][nt][2]), kb);
                    }
                    if (acc[mt][nt][3] >= cutB) {
                        int p = atomicAdd(&scnt[rB], 1);
                        if (p < CAP) g_cand[(size_t)(row0 + rB) * CAP + p] =
                            make_int2(__float_as_int(acc[mt][nt][3]), kb + 1);
                    }
                }
            }
        }
        __syncthreads();
    }

    if (tid < 128) g_ccnt[row0 + tid] = scnt[tid];
}

// ---------------------------------------------------------------------------
// rescore: global-max pruning on stored bf16 scores, then exact fp32 chains
// (per-candidate arithmetic identical to R1-R6). 16 lanes/row, 2 rows/warp.
// ---------------------------------------------------------------------------
__global__ void __launch_bounds__(256) k_rescore(
    const float* __restrict__ X, const float* __restrict__ E)
{
    __shared__ float xs[16][132];
    const int warp = threadIdx.x >> 5;
    const int lane = threadIdx.x & 31;
    const int grp  = lane >> 4;     // 0..1: row within warp
    const int l16  = lane & 15;     // lane within 16-lane group
    const int rowL = warp * 2 + grp;
    const int row  = blockIdx.x * 16 + rowL;

    for (int i = threadIdx.x; i < 16 * 32; i += 256) {
        int r = i >> 5, c = i & 31;
        float4 v = ((const float4*)X)[(size_t)(blockIdx.x * 16 + r) * 32 + c];
        *(float4*)&xs[r][c * 4] = v;
    }
    __syncthreads();

    const float* xr = xs[rowL];
    // A = |x|^2 in fp64, reduced within the 16-lane group
    double s = 0.0;
    #pragma unroll
    for (int i = 0; i < 8; i++) { double v = (double)xr[l16 * 8 + i]; s += v * v; }
    #pragma unroll
    for (int off = 1; off < 16; off <<= 1)
        s += __shfl_xor_sync(0xffffffffu, s, off);
    float A = (float)s;

    int n = g_ccnt[row];
    float best = CUDART_INF_F;
    int bi = 0x7fffffff;

    if (n <= CAP) {
        const int2* cd = &g_cand[(size_t)row * CAP];
        // pass A: global bf16-score max over this row's candidates
        float vmax = -CUDART_INF_F;
        for (int j = l16; j < n; j += 16)
            vmax = fmaxf(vmax, __int_as_float(cd[j].x));
        #pragma unroll
        for (int off = 1; off < 16; off <<= 1)
            vmax = fmaxf(vmax, __shfl_xor_sync(0xffffffffu, vmax, off));
        const float cut = vmax - DELTA_C;
        // pass B: exact fp32 chain only for survivors
        for (int j = l16; j < n; j += 16) {
            int2 c = cd[j];
            if (__int_as_float(c.x) < cut) continue;
            int k = c.y;
            const float4* e4 = (const float4*)(E + (size_t)k * D_N);
            float acc = 0.0f;
            #pragma unroll 8
            for (int i = 0; i < 32; i++) {
                float4 xv = *(const float4*)&xr[i * 4];
                float4 ev = e4[i];
                acc = __fmaf_rn(xv.x, ev.x, acc);
                acc = __fmaf_rn(xv.y, ev.y, acc);
                acc = __fmaf_rn(xv.z, ev.z, acc);
                acc = __fmaf_rn(xv.w, ev.w, acc);
            }
            float tsum = __fadd_rn(A, g_esq[k]);
            float v = __fmaf_rn(-2.0f, acc, tsum);
            if (v < best || (v == best && k < bi)) { best = v; bi = k; }
        }
    } else {
        // safety fallback: exact full scan (unreachable in practice with CAP=128)
        for (int k = l16; k < K_N; k += 16) {
            const float4* e4 = (const float4*)(E + (size_t)k * D_N);
            float acc = 0.0f;
            #pragma unroll 8
            for (int i = 0; i < 32; i++) {
                float4 xv = *(const float4*)&xr[i * 4];
                float4 ev = e4[i];
                acc = __fmaf_rn(xv.x, ev.x, acc);
                acc = __fmaf_rn(xv.y, ev.y, acc);
                acc = __fmaf_rn(xv.z, ev.z, acc);
                acc = __fmaf_rn(xv.w, ev.w, acc);
            }
            float tsum = __fadd_rn(A, g_esq[k]);
            float v = __fmaf_rn(-2.0f, acc, tsum);
            if (v < best || (v == best && k < bi)) { best = v; bi = k; }
        }
    }
    // butterfly reduce within 16-lane group, lexicographic (v, k)
    #pragma unroll
    for (int off = 1; off < 16; off <<= 1) {
        float ov = __shfl_xor_sync(0xffffffffu, best, off);
        int   oi = __shfl_xor_sync(0xffffffffu, bi, off);
        if (ov < best || (ov == best && oi < bi)) { best = ov; bi = oi; }
    }
    if (l16 == 0) g_argmin[row] = bi;
}

// ---------------------------------------------------------------------------
// gather: quantized rows + straight-through output + loss sums + histogram
// ---------------------------------------------------------------------------
__global__ void k_gather(const float* __restrict__ X, const float* __restrict__ E,
                         float* __restrict__ out, int out_size)
{
    int g = blockIdx.x * blockDim.x + threadIdx.x;
    int b = g >> 5, j = g & 31;
    int idx = g_argmin[b];

    float4 q = ((const float4*)E)[(size_t)idx * 32 + j];
    float4 x = ((const float4*)X)[g];

    float4 o;
    double se = 0.0, sq = 0.0;
    {
        float de = __fsub_rn(q.x, x.x); float qs = __fadd_rn(x.x, de);
        float dq = __fsub_rn(qs, x.x);
        o.x = qs; se += (double)de * (double)de; sq += (double)dq * (double)dq;
    }
    {
        float de = __fsub_rn(q.y, x.y); float qs = __fadd_rn(x.y, de);
        float dq = __fsub_rn(qs, x.y);
        o.y = qs; se += (double)de * (double)de; sq += (double)dq * (double)dq;
    }
    {
        float de = __fsub_rn(q.z, x.z); float qs = __fadd_rn(x.z, de);
        float dq = __fsub_rn(qs, x.z);
        o.z = qs; se += (double)de * (double)de; sq += (double)dq * (double)dq;
    }
    {
        float de = __fsub_rn(q.w, x.w); float qs = __fadd_rn(x.w, de);
        float dq = __fsub_rn(qs, x.w);
        o.w = qs; se += (double)de * (double)de; sq += (double)dq * (double)dq;
    }
    ((float4*)out)[g] = o;

    if (j == 0) {
        atomicAdd(&g_counts[idx], 1);
        if (out_size >= B_N * D_N + B_N)
            out[(size_t)B_N * D_N + b] = (float)idx;
    }

    #pragma unroll
    for (int off = 16; off > 0; off >>= 1) {
        se += __shfl_down_sync(0xffffffffu, se, off);
        sq += __shfl_down_sync(0xffffffffu, sq, off);
    }
    __shared__ double swe[8], swq[8];
    int lane = threadIdx.x & 31, w = threadIdx.x >> 5;
    if (lane == 0) { swe[w] = se; swq[w] = sq; }
    __syncthreads();
    if (threadIdx.x == 0) {
        double te = 0.0, tq = 0.0;
        #pragma unroll
        for (int i = 0; i < 8; i++) { te += swe[i]; tq += swq[i]; }
        atomicAdd(&g_sum_e, te);
        atomicAdd(&g_sum_q, tq);
    }
}

// ---------------------------------------------------------------------------
__global__ void k_entropy() {
    __shared__ double sh[256];
    int k = blockIdx.x * 256 + threadIdx.x;
    float p = __fmul_rn((float)g_counts[k], 1.0f / 32768.0f);
    float t = __fmul_rn(p, logf(__fadd_rn(p, 1e-10f)));
    sh[threadIdx.x] = (double)t;
    __syncthreads();
    for (int s = 128; s > 0; s >>= 1) {
        if (threadIdx.x < s) sh[threadIdx.x] += sh[threadIdx.x + s];
        __syncthreads();
    }
    if (threadIdx.x == 0) atomicAdd(&g_H, sh[0]);
}

__global__ void k_scalars(float* __restrict__ out, int out_size) {
    if (out_size < B_N * D_N + B_N + 4) return;
    float H = (float)g_H;
    float perp = expf(-H);
    double n = (double)B_N * (double)D_N;
    float e = (float)(g_sum_e / n);
    float q = (float)(g_sum_q / n);
    float vq = __fadd_rn(q, __fmul_rn(0.25f, e));
    float* s4 = out + (size_t)B_N * D_N + B_N;
    s4[0] = vq; s4[1] = e; s4[2] = q; s4[3] = perp;
}

// ---------------------------------------------------------------------------
extern "C" void kernel_launch(void* const* d_in, const int* in_sizes, int n_in,
                              void* d_out, int out_size)
{
    const float* X = (const float*)d_in[0];
    const float* E = (const float*)d_in[1];
    if (n_in >= 2 && in_sizes[0] == K_N * D_N && in_sizes[1] == B_N * D_N) {
        X = (const float*)d_in[1];
        E = (const float*)d_in[0];
    }
    float* out = (float*)d_out;

    static bool attr_set = false;
    if (!attr_set) {
        cudaFuncSetAttribute(k_phase1,
                             cudaFuncAttributeMaxDynamicSharedMemorySize,
                             SM_TOTAL);
        attr_set = true;
    }

    int ngroups = (B_N * D_N + K_N * D_N) / 8;
    k_convert<<<(ngroups + 255) / 256, 256>>>(X, E);
    k_init<<<(K_N + 255) / 256, 256>>>(E);
    k_phase1<<<B_N / 128, 256, SM_TOTAL>>>();
    k_rescore<<<B_N / 16, 256>>>(X, E);
    k_gather<<<(B_N * D_N / 4) / 256, 256>>>(X, E, out, out_size);
    k_entropy<<<K_N / 256, 256>>>();
    k_scalars<<<1, 1>>>(out, out_size);
}

// round 8
// speedup vs baseline: 2.0504x; 1.1905x over previous
#include <cuda_runtime.h>
#include <cuda_bf16.h>
#include <math_constants.h>
#include <cstdint>

#define B_N 32768
#define D_N 128
#define K_N 4096
#define CAP 128
#define DELTA_C 2.5e-4f
#define NTILES 32

// phase-1 smem layout (bytes). Rows padded to 272B (136 bf16) for conflict-free LDSM.
#define ROWB 272
#define XS_OFF   0
#define E0_OFF   34816
#define E1_OFF   69632
#define SCNT_OFF 104448
#define SM_TOTAL 104960

__device__ __nv_bfloat16 g_eb[K_N * D_N];
__device__ int2   g_cand[(size_t)B_N * CAP];   // .x = bf16-GEMM score bits, .y = index
__device__ int    g_ccnt[B_N];
__device__ float  g_esq[K_N];
__device__ int    g_counts[K_N];
__device__ double g_sum_e, g_sum_q;

__device__ __forceinline__ uint32_t smem_u32(const void* p) {
    uint32_t a;
    asm("{ .reg .u64 t; cvta.to.shared.u64 t, %1; cvt.u32.u64 %0, t; }"
        : "=r"(a) : "l"(p));
    return a;
}
__device__ __forceinline__ void ldsm_x4(uint32_t& r0, uint32_t& r1,
                                        uint32_t& r2, uint32_t& r3, uint32_t addr) {
    asm volatile("ldmatrix.sync.aligned.m8n8.x4.shared.b16 {%0,%1,%2,%3}, [%4];"
        : "=r"(r0), "=r"(r1), "=r"(r2), "=r"(r3) : "r"(addr));
}
__device__ __forceinline__ void mma16816(float* c, uint32_t a0, uint32_t a1,
                                         uint32_t a2, uint32_t a3,
                                         uint32_t b0, uint32_t b1) {
    asm volatile("mma.sync.aligned.m16n8k16.row.col.f32.bf16.bf16.f32 "
        "{%0,%1,%2,%3}, {%4,%5,%6,%7}, {%8,%9}, {%0,%1,%2,%3};"
        : "+f"(c[0]), "+f"(c[1]), "+f"(c[2]), "+f"(c[3])
        : "r"(a0), "r"(a1), "r"(a2), "r"(a3), "r"(b0), "r"(b1));
}
__device__ __forceinline__ uint32_t packbf(float a, float b) {
    return ((uint32_t)__bfloat16_as_ushort(__float2bfloat16_rn(b)) << 16) |
            (uint32_t)__bfloat16_as_ushort(__float2bfloat16_rn(a));
}
#define CP_ASYNC16(dst, src) \
    asm volatile("cp.async.cg.shared.global [%0], [%1], 16;" \
        :: "r"(dst), "l"(src) : "memory")
#define CP_COMMIT() asm volatile("cp.async.commit_group;" ::: "memory")
#define CP_WAIT(n)  asm volatile("cp.async.wait_group %0;" :: "n"(n) : "memory")

// ---------------------------------------------------------------------------
// init: warp per E row — |e|^2 (fp64, shuffle-reduced), bf16 convert, zeroing
// ---------------------------------------------------------------------------
__global__ void __launch_bounds__(256) k_init(const float* __restrict__ E) {
    const int warp = threadIdx.x >> 5;
    const int lane = threadIdx.x & 31;
    const int row  = blockIdx.x * 8 + warp;

    float4 v = ((const float4*)(E + (size_t)row * D_N))[lane];
    double s = 0.0;
    s += (double)v.x * (double)v.x;
    s += (double)v.y * (double)v.y;
    s += (double)v.z * (double)v.z;
    s += (double)v.w * (double)v.w;
    #pragma unroll
    for (int off = 16; off > 0; off >>= 1)
        s += __shfl_xor_sync(0xffffffffu, s, off);

    uint2 o;
    o.x = packbf(v.x, v.y);
    o.y = packbf(v.z, v.w);
    ((uint2*)g_eb)[(size_t)row * 32 + lane] = o;

    if (lane == 0) { g_esq[row] = (float)s; g_counts[row] = 0; }
    if (row == 0 && lane == 0) { g_sum_e = 0.0; g_sum_q = 0.0; }
}

// ---------------------------------------------------------------------------
// phase1: bf16 mma.sync GEMM C = X_b @ E_b^T with per-half register-threshold
// candidate selection (stores (score,index) pairs). X converted fp32->bf16 in
// the prologue; E tiles staged via cp.async double-buffering.
// ---------------------------------------------------------------------------
__global__ void __launch_bounds__(256, 2) k_phase1(const float* __restrict__ X) {
    extern __shared__ char smem[];
    int* scnt = (int*)(smem + SCNT_OFF);   // [128]

    const int tid  = threadIdx.x;
    const int lane = tid & 31;
    const int wid  = tid >> 5;
    const int wm   = wid >> 1;          // 0..3  (rows 32*wm .. +32)
    const int wn   = wid & 1;           // 0..1  (cols 64*wn .. +64)
    const int row0 = blockIdx.x * 128;

    if (tid < 128) scnt[tid] = 0;

    const uint32_t sb = smem_u32(smem);

    // issue E tile 0 via cp.async (group 0)
    #pragma unroll
    for (int i = 0; i < 8; i++) {
        int m = tid + i * 256; int r = m >> 4, c16 = m & 15;
        uint32_t dst = sb + E0_OFF + (uint32_t)(r * ROWB + c16 * 16);
        const char* src = (const char*)g_eb + (size_t)r * 256 + c16 * 16;
        CP_ASYNC16(dst, src);
    }
    CP_COMMIT();

    // X tile: load fp32, convert to bf16, store padded (overlaps with cp.async)
    #pragma unroll
    for (int i = 0; i < 8; i++) {
        int m = tid + i * 256; int r = m >> 4, c16 = m & 15;
        float4 f0 = ((const float4*)X)[(size_t)(row0 + r) * 32 + c16 * 2];
        float4 f1 = ((const float4*)X)[(size_t)(row0 + r) * 32 + c16 * 2 + 1];
        uint4 o;
        o.x = packbf(f0.x, f0.y);
        o.y = packbf(f0.z, f0.w);
        o.z = packbf(f1.x, f1.y);
        o.w = packbf(f1.z, f1.w);
        *(uint4*)(smem + XS_OFF + r * ROWB + c16 * 16) = o;
    }

    const uint32_t pA = sb + XS_OFF + (uint32_t)((wm * 32 + (lane & 15)) * ROWB)
                        + (uint32_t)((lane >> 4) * 8 * 2);
    const int n_lane = ((lane >> 4) << 3) + (lane & 7);
    const uint32_t pB_off = (uint32_t)((wn * 64 + n_lane) * ROWB)
                            + (uint32_t)(((lane >> 3) & 1) * 8 * 2);

    const int qr = lane >> 2;           // quad row id 0..7
    const int qc = lane & 3;

    // per-half running row maxima (registers)
    float thrA[2] = { -CUDART_INF_F, -CUDART_INF_F };
    float thrB[2] = { -CUDART_INF_F, -CUDART_INF_F };

    for (int t = 0; t < NTILES; t++) {
        const int buf = t & 1;

        // stage tile t+1 into the other buffer, then wait for tile t
        if (t + 1 < NTILES) {
            const int nb = (t + 1) & 1;
            const uint32_t ebase = sb + (nb ? E1_OFF : E0_OFF);
            #pragma unroll
            for (int i = 0; i < 8; i++) {
                int m = tid + i * 256; int r = m >> 4, c16 = m & 15;
                uint32_t dst = ebase + (uint32_t)(r * ROWB + c16 * 16);
                const char* src = (const char*)g_eb
                                  + (size_t)((t + 1) * 128 + r) * 256 + c16 * 16;
                CP_ASYNC16(dst, src);
            }
            CP_COMMIT();
            CP_WAIT(1);
        } else {
            CP_WAIT(0);
        }
        __syncthreads();

        const uint32_t pB = sb + (buf ? E1_OFF : E0_OFF) + pB_off;

        float acc[2][8][4];
        #pragma unroll
        for (int mt = 0; mt < 2; mt++)
            #pragma unroll
            for (int nt = 0; nt < 8; nt++)
                #pragma unroll
                for (int j = 0; j < 4; j++) acc[mt][nt][j] = 0.0f;

        #pragma unroll
        for (int s = 0; s < 8; s++) {
            uint32_t a[2][4];
            #pragma unroll
            for (int mt = 0; mt < 2; mt++)
                ldsm_x4(a[mt][0], a[mt][1], a[mt][2], a[mt][3],
                        pA + (uint32_t)(mt * 16 * ROWB) + (uint32_t)(s * 32));
            uint32_t b[4][4];
            #pragma unroll
            for (int p = 0; p < 4; p++)
                ldsm_x4(b[p][0], b[p][1], b[p][2], b[p][3],
                        pB + (uint32_t)(p * 16 * ROWB) + (uint32_t)(s * 32));
            #pragma unroll
            for (int mt = 0; mt < 2; mt++)
                #pragma unroll
                for (int nt = 0; nt < 8; nt++) {
                    uint32_t b0 = (nt & 1) ? b[nt >> 1][2] : b[nt >> 1][0];
                    uint32_t b1 = (nt & 1) ? b[nt >> 1][3] : b[nt >> 1][1];
                    mma16816(acc[mt][nt], a[mt][0], a[mt][1], a[mt][2], a[mt][3], b0, b1);
                }
        }

        // ---- epilogue: warp-local row maxima, guarded emission ----
        #pragma unroll
        for (int mt = 0; mt < 2; mt++) {
            float ma = -CUDART_INF_F, mb = -CUDART_INF_F;
            #pragma unroll
            for (int nt = 0; nt < 8; nt++) {
                ma = fmaxf(ma, fmaxf(acc[mt][nt][0], acc[mt][nt][1]));
                mb = fmaxf(mb, fmaxf(acc[mt][nt][2], acc[mt][nt][3]));
            }
            ma = fmaxf(ma, __shfl_xor_sync(0xffffffffu, ma, 1));
            ma = fmaxf(ma, __shfl_xor_sync(0xffffffffu, ma, 2));
            mb = fmaxf(mb, __shfl_xor_sync(0xffffffffu, mb, 1));
            mb = fmaxf(mb, __shfl_xor_sync(0xffffffffu, mb, 2));
            const bool anyA = (ma >= thrA[mt] - DELTA_C);
            const bool anyB = (mb >= thrB[mt] - DELTA_C);
            thrA[mt] = fmaxf(thrA[mt], ma);
            thrB[mt] = fmaxf(thrB[mt], mb);
            const int rA = wm * 32 + mt * 16 + qr;
            const int rB = rA + 8;
            if (anyA) {
                const float cutA = thrA[mt] - DELTA_C;
                #pragma unroll
                for (int nt = 0; nt < 8; nt++) {
                    int kb = t * 128 + wn * 64 + nt * 8 + 2 * qc;
                    if (acc[mt][nt][0] >= cutA) {
                        int p = atomicAdd(&scnt[rA], 1);
                        if (p < CAP) g_cand[(size_t)(row0 + rA) * CAP + p] =
                            make_int2(__float_as_int(acc[mt][nt][0]), kb);
                    }
                    if (acc[mt][nt][1] >= cutA) {
                        int p = atomicAdd(&scnt[rA], 1);
                        if (p < CAP) g_cand[(size_t)(row0 + rA) * CAP + p] =
                            make_int2(__float_as_int(acc[mt][nt][1]), kb + 1);
                    }
                }
            }
            if (anyB) {
                const float cutB = thrB[mt] - DELTA_C;
                #pragma unroll
                for (int nt = 0; nt < 8; nt++) {
                    int kb = t * 128 + wn * 64 + nt * 8 + 2 * qc;
                    if (acc[mt][nt][2] >= cutB) {
                        int p = atomicAdd(&scnt[rB], 1);
                        if (p < CAP) g_cand[(size_t)(row0 + rB) * CAP + p] =
                            make_int2(__float_as_int(acc[mt][nt][2]), kb);
                    }
                    if (acc[mt][nt][3] >= cutB) {
                        int p = atomicAdd(&scnt[rB], 1);
                        if (p < CAP) g_cand[(size_t)(row0 + rB) * CAP + p] =
                            make_int2(__float_as_int(acc[mt][nt][3]), kb + 1);
                    }
                }
            }
        }
        __syncthreads();   // buf(t) reads done before next iteration's cp.async
    }

    if (tid < 128) g_ccnt[row0 + tid] = scnt[tid];
}

// ---------------------------------------------------------------------------
// rescore + gather (fused): global-max prune on stored bf16 scores, exact fp32
// chains (arithmetic identical to R1-R7), then straight-through output, loss
// sums and histogram using the same smem X. 16 lanes/row, 2 rows/warp.
// ---------------------------------------------------------------------------
__global__ void __launch_bounds__(256) k_rescore_gather(
    const float* __restrict__ X, const float* __restrict__ E,
    float* __restrict__ out, int out_size)
{
    __shared__ float xs[16][132];
    __shared__ double swe[8], swq[8];
    const int warp = threadIdx.x >> 5;
    const int lane = threadIdx.x & 31;
    const int grp  = lane >> 4;     // 0..1: row within warp
    const int l16  = lane & 15;     // lane within 16-lane group
    const int rowL = warp * 2 + grp;
    const int row  = blockIdx.x * 16 + rowL;

    for (int i = threadIdx.x; i < 16 * 32; i += 256) {
        int r = i >> 5, c = i & 31;
        float4 v = ((const float4*)X)[(size_t)(blockIdx.x * 16 + r) * 32 + c];
        *(float4*)&xs[r][c * 4] = v;
    }
    __syncthreads();

    const float* xr = xs[rowL];
    // A = |x|^2 in fp64, reduced within the 16-lane group
    double s = 0.0;
    #pragma unroll
    for (int i = 0; i < 8; i++) { double v = (double)xr[l16 * 8 + i]; s += v * v; }
    #pragma unroll
    for (int off = 1; off < 16; off <<= 1)
        s += __shfl_xor_sync(0xffffffffu, s, off);
    float A = (float)s;

    int n = g_ccnt[row];
    float best = CUDART_INF_F;
    int bi = 0x7fffffff;

    if (n <= CAP) {
        const int2* cd = &g_cand[(size_t)row * CAP];
        // pass A: global bf16-score max over this row's candidates
        float vmax = -CUDART_INF_F;
        for (int j = l16; j < n; j += 16)
            vmax = fmaxf(vmax, __int_as_float(cd[j].x));
        #pragma unroll
        for (int off = 1; off < 16; off <<= 1)
            vmax = fmaxf(vmax, __shfl_xor_sync(0xffffffffu, vmax, off));
        const float cut = vmax - DELTA_C;
        // pass B: exact fp32 chain only for survivors
        for (int j = l16; j < n; j += 16) {
            int2 c = cd[j];
            if (__int_as_float(c.x) < cut) continue;
            int k = c.y;
            const float4* e4 = (const float4*)(E + (size_t)k * D_N);
            float acc = 0.0f;
            #pragma unroll 8
            for (int i = 0; i < 32; i++) {
                float4 xv = *(const float4*)&xr[i * 4];
                float4 ev = e4[i];
                acc = __fmaf_rn(xv.x, ev.x, acc);
                acc = __fmaf_rn(xv.y, ev.y, acc);
                acc = __fmaf_rn(xv.z, ev.z, acc);
                acc = __fmaf_rn(xv.w, ev.w, acc);
            }
            float tsum = __fadd_rn(A, g_esq[k]);
            float v = __fmaf_rn(-2.0f, acc, tsum);
            if (v < best || (v == best && k < bi)) { best = v; bi = k; }
        }
    } else {
        // safety fallback: exact full scan (unreachable in practice)
        for (int k = l16; k < K_N; k += 16) {
            const float4* e4 = (const float4*)(E + (size_t)k * D_N);
            float acc = 0.0f;
            #pragma unroll 8
            for (int i = 0; i < 32; i++) {
                float4 xv = *(const float4*)&xr[i * 4];
                float4 ev = e4[i];
                acc = __fmaf_rn(xv.x, ev.x, acc);
                acc = __fmaf_rn(xv.y, ev.y, acc);
                acc = __fmaf_rn(xv.z, ev.z, acc);
                acc = __fmaf_rn(xv.w, ev.w, acc);
            }
            float tsum = __fadd_rn(A, g_esq[k]);
            float v = __fmaf_rn(-2.0f, acc, tsum);
            if (v < best || (v == best && k < bi)) { best = v; bi = k; }
        }
    }
    // butterfly reduce within 16-lane group -> all lanes hold (best, bi)
    #pragma unroll
    for (int off = 1; off < 16; off <<= 1) {
        float ov = __shfl_xor_sync(0xffffffffu, best, off);
        int   oi = __shfl_xor_sync(0xffffffffu, bi, off);
        if (ov < best || (ov == best && oi < bi)) { best = ov; bi = oi; }
    }

    // ---- gather: straight-through output + loss sums + histogram ----
    const float4* e4 = (const float4*)(E + (size_t)bi * D_N);
    float4 q0 = e4[l16 * 2], q1 = e4[l16 * 2 + 1];
    float4 x0 = *(const float4*)&xr[l16 * 8];
    float4 x1 = *(const float4*)&xr[l16 * 8 + 4];
    float4 o0, o1;
    double se = 0.0, sq = 0.0;
#define VQ_STEP(o, q, x) { \
        float de = __fsub_rn(q, x); float qs = __fadd_rn(x, de); \
        float dq = __fsub_rn(qs, x); \
        o = qs; se += (double)de * (double)de; sq += (double)dq * (double)dq; }
    VQ_STEP(o0.x, q0.x, x0.x)  VQ_STEP(o0.y, q0.y, x0.y)
    VQ_STEP(o0.z, q0.z, x0.z)  VQ_STEP(o0.w, q0.w, x0.w)
    VQ_STEP(o1.x, q1.x, x1.x)  VQ_STEP(o1.y, q1.y, x1.y)
    VQ_STEP(o1.z, q1.z, x1.z)  VQ_STEP(o1.w, q1.w, x1.w)
#undef VQ_STEP
    ((float4*)out)[(size_t)row * 32 + l16 * 2]     = o0;
    ((float4*)out)[(size_t)row * 32 + l16 * 2 + 1] = o1;

    if (l16 == 0) {
        atomicAdd(&g_counts[bi], 1);
        if (out_size >= B_N * D_N + B_N)
            out[(size_t)B_N * D_N + row] = (float)bi;
    }

    // block-reduce loss sums
    #pragma unroll
    for (int off = 16; off > 0; off >>= 1) {
        se += __shfl_down_sync(0xffffffffu, se, off);
        sq += __shfl_down_sync(0xffffffffu, sq, off);
    }
    if (lane == 0) { swe[warp] = se; swq[warp] = sq; }
    __syncthreads();
    if (threadIdx.x == 0) {
        double te = 0.0, tq = 0.0;
        #pragma unroll
        for (int i = 0; i < 8; i++) { te += swe[i]; tq += swq[i]; }
        atomicAdd(&g_sum_e, te);
        atomicAdd(&g_sum_q, tq);
    }
}

// ---------------------------------------------------------------------------
// final: entropy + scalar outputs in one kernel (single CTA)
// ---------------------------------------------------------------------------
__global__ void k_final(float* __restrict__ out, int out_size) {
    if (out_size < B_N * D_N + B_N + 4) return;
    __shared__ double sh[512];
    int tid = threadIdx.x;
    double h = 0.0;
    #pragma unroll
    for (int r = 0; r < K_N / 512; r++) {
        int k = r * 512 + tid;
        float p = __fmul_rn((float)g_counts[k], 1.0f / 32768.0f);
        float t = __fmul_rn(p, logf(__fadd_rn(p, 1e-10f)));
        h += (double)t;
    }
    sh[tid] = h;
    __syncthreads();
    for (int s = 256; s > 0; s >>= 1) {
        if (tid < s) sh[tid] += sh[tid + s];
        __syncthreads();
    }
    if (tid == 0) {
        float H = (float)sh[0];
        float perp = expf(-H);
        double n = (double)B_N * (double)D_N;
        float e = (float)(g_sum_e / n);
        float q = (float)(g_sum_q / n);
        float vq = __fadd_rn(q, __fmul_rn(0.25f, e));
        float* s4 = out + (size_t)B_N * D_N + B_N;
        s4[0] = vq; s4[1] = e; s4[2] = q; s4[3] = perp;
    }
}

// ---------------------------------------------------------------------------
extern "C" void kernel_launch(void* const* d_in, const int* in_sizes, int n_in,
                              void* d_out, int out_size)
{
    const float* X = (const float*)d_in[0];
    const float* E = (const float*)d_in[1];
    if (n_in >= 2 && in_sizes[0] == K_N * D_N && in_sizes[1] == B_N * D_N) {
        X = (const float*)d_in[1];
        E = (const float*)d_in[0];
    }
    float* out = (float*)d_out;

    static bool attr_set = false;
    if (!attr_set) {
        cudaFuncSetAttribute(k_phase1,
                             cudaFuncAttributeMaxDynamicSharedMemorySize,
                             SM_TOTAL);
        attr_set = true;
    }

    k_init<<<K_N / 8, 256>>>(E);
    k_phase1<<<B_N / 128, 256, SM_TOTAL>>>(X);
    k_rescore_gather<<<B_N / 16, 256>>>(X, E, out, out_size);
    k_final<<<1, 512>>>(out, out_size);
}